// round 10
// baseline (speedup 1.0000x reference)
#include <cuda_runtime.h>
#include <cuda_bf16.h>

#define NNODES 100000
#define NEDGES 600000
#define DFEAT  128

// Scratch
__device__ float g_dis[NNODES];    // deg -> rsqrt(deg)
__device__ float g_s[NNODES];      // raw dot products x·w
__device__ float g_p[NNODES];      // p0 = dis * s
__device__ float g_acc[NNODES];    // round-1 accumulator (init = p0)
__device__ float g_p2[NNODES];     // p1 = dis^2 * acc1
__device__ float g_acc2[NNODES];   // round-2 accumulator (init = p1)

// K1: deg = 1 (self loop)
__global__ void k_init() {
    int i = blockIdx.x * blockDim.x + threadIdx.x;
    if (i < NNODES) g_dis[i] = 1.0f;
}

// K2: degree count, 2 edges/thread — runs on forked stream, concurrent with k_dot
__global__ void k_count_deg(const int* __restrict__ ei) {
    int e = (blockIdx.x * blockDim.x + threadIdx.x) * 2;
    if (e < NEDGES) {
        int2 c2 = *reinterpret_cast<const int2*>(ei + NEDGES + e);
        atomicAdd(&g_dis[c2.x], 1.0f);
        atomicAdd(&g_dis[c2.y], 1.0f);
    }
}

// K3: s = x·w per node (4 nodes/warp, MLP=4). Touches only x, w, g_s
// -> fully independent of k_count_deg.
__global__ void k_dot(const float* __restrict__ x, const float* __restrict__ w) {
    int warp_id = (blockIdx.x * blockDim.x + threadIdx.x) >> 5;
    int lane = threadIdx.x & 31;
    int base = warp_id * 4;
    if (base >= NNODES) return;   // NNODES % 4 == 0

    const float4* wr = reinterpret_cast<const float4*>(w);
    float4 wv = __ldg(&wr[lane]);

    float4 xv0 = reinterpret_cast<const float4*>(x + (size_t)(base + 0) * DFEAT)[lane];
    float4 xv1 = reinterpret_cast<const float4*>(x + (size_t)(base + 1) * DFEAT)[lane];
    float4 xv2 = reinterpret_cast<const float4*>(x + (size_t)(base + 2) * DFEAT)[lane];
    float4 xv3 = reinterpret_cast<const float4*>(x + (size_t)(base + 3) * DFEAT)[lane];

    float s0 = xv0.x * wv.x + xv0.y * wv.y + xv0.z * wv.z + xv0.w * wv.w;
    float s1 = xv1.x * wv.x + xv1.y * wv.y + xv1.z * wv.z + xv1.w * wv.w;
    float s2 = xv2.x * wv.x + xv2.y * wv.y + xv2.z * wv.z + xv2.w * wv.w;
    float s3 = xv3.x * wv.x + xv3.y * wv.y + xv3.z * wv.z + xv3.w * wv.w;

    #pragma unroll
    for (int off = 16; off > 0; off >>= 1) {
        s0 += __shfl_xor_sync(0xFFFFFFFFu, s0, off);
        s1 += __shfl_xor_sync(0xFFFFFFFFu, s1, off);
        s2 += __shfl_xor_sync(0xFFFFFFFFu, s2, off);
        s3 += __shfl_xor_sync(0xFFFFFFFFu, s3, off);
    }

    if (lane == 0) {
        *reinterpret_cast<float4*>(&g_s[base]) = make_float4(s0, s1, s2, s3);
    }
}

// K4 (join point): dis = rsqrt(deg); p0 = dis*s; acc1 init = p0
__global__ void k_norm() {
    int i = blockIdx.x * blockDim.x + threadIdx.x;
    if (i < NNODES) {
        float d = rsqrtf(g_dis[i]);
        g_dis[i] = d;
        float p = d * g_s[i];
        g_p[i]   = p;
        g_acc[i] = p;
    }
}

// K5: round-1 edges: acc1[col] += p0[row]; 1 edge/thread (wavefront floor)
__global__ void k_edge1(const int* __restrict__ ei) {
    int e = blockIdx.x * blockDim.x + threadIdx.x;
    if (e < NEDGES) {
        int row = __ldg(&ei[e]);
        int col = __ldg(&ei[NEDGES + e]);
        atomicAdd(&g_acc[col], __ldg(&g_p[row]));
    }
}

// K6: p1 = dis^2 * acc1 ; acc2 init = p1
__global__ void k_pre2() {
    int i = blockIdx.x * blockDim.x + threadIdx.x;
    if (i < NNODES) {
        float dd = g_dis[i];
        float v = dd * dd * g_acc[i];
        g_p2[i]   = v;
        g_acc2[i] = v;
    }
}

// K7: round-2 edges: acc2[col] += p1[row]
__global__ void k_edge2(const int* __restrict__ ei) {
    int e = blockIdx.x * blockDim.x + threadIdx.x;
    if (e < NEDGES) {
        int row = __ldg(&ei[e]);
        int col = __ldg(&ei[NEDGES + e]);
        atomicAdd(&g_acc2[col], __ldg(&g_p2[row]));
    }
}

// K8: out = dis * acc2 + b
__global__ void k_post(float* __restrict__ out, const float* __restrict__ b) {
    int i = blockIdx.x * blockDim.x + threadIdx.x;
    if (i < NNODES) {
        out[i] = g_dis[i] * g_acc2[i] + b[0];
    }
}

extern "C" void kernel_launch(void* const* d_in, const int* in_sizes, int n_in,
                              void* d_out, int out_size) {
    const float* x  = (const float*)d_in[0];
    const int*   ei = (const int*)d_in[1];
    const float* W  = (const float*)d_in[2];
    const float* b  = (const float*)d_in[3];
    float* out = (float*)d_out;

    // One-time host-side handles (no device memory involved). Created on the
    // first (correctness) call, outside graph capture; identical GPU work
    // is issued on every call.
    static cudaStream_t s_branch = nullptr;
    static cudaEvent_t  ev_fork = nullptr, ev_join = nullptr;
    if (s_branch == nullptr) {
        cudaStreamCreateWithFlags(&s_branch, cudaStreamNonBlocking);
        cudaEventCreateWithFlags(&ev_fork, cudaEventDisableTiming);
        cudaEventCreateWithFlags(&ev_join, cudaEventDisableTiming);
    }

    const int T = 256;
    const int gN   = (NNODES + T - 1) / T;
    const int gE   = (NEDGES + T - 1) / T;        // 1 edge/thread
    const int gE2  = (NEDGES / 2 + T - 1) / T;    // 2 edges/thread
    const int gDot = ((NNODES / 4) * 32 + T - 1) / T;

    // deg = 1 first (count_deg accumulates onto it)
    k_init<<<gN, T>>>();

    // fork: count on s_branch, dot on main stream — independent, overlapped
    cudaEventRecord(ev_fork, 0);
    cudaStreamWaitEvent(s_branch, ev_fork, 0);
    k_count_deg<<<gE2, T, 0, s_branch>>>(ei);
    k_dot<<<gDot, T>>>(x, W);
    cudaEventRecord(ev_join, s_branch);
    cudaStreamWaitEvent(0, ev_join, 0);

    // join: normalization + both propagation rounds
    k_norm<<<gN, T>>>();
    k_edge1<<<gE, T>>>(ei);
    k_pre2<<<gN, T>>>();
    k_edge2<<<gE, T>>>(ei);
    k_post<<<gN, T>>>(out, b);
}